// round 4
// baseline (speedup 1.0000x reference)
#include <cuda_runtime.h>
#include <math.h>

// FineMatchingModule — algebraically collapsed form (verified R3, rel_err 1.4e-8):
// both attention layers add only window-uniform shifts, which the final softmax
// cancels. Remaining computation per point:
//   corr[n] = sum_j s[j] * flat[n*256+j],  n = 0..24
// where flat is the channel-major-flattened zero-padded 5x5 window of
// target_features at the truncated coarse position, and s is the center pixel's
// channel vector. refined = pos + softmax(corr) @ offsets,
// offsets1d = linspace(-3, 2, 5).
//
// This version: one CTA (256 threads) per point, one CHANNEL per thread.
// flat[idx] with idx = 25*ch + p means each thread's 25 products (p = 0..24)
// are direct coalesced gmem loads (lane = ch, same pixel) and hit at most two
// tokens n = idx>>8 -> two register accumulators + <=2 smem atomicAdds.
// No 25.6KB staging tile, no transpose, smem = 1.2KB.

#define B_ 4
#define K_ 1024
#define H_ 256
#define W_ 256
#define C_ 256

__global__ __launch_bounds__(256)
void fine_match_kernel(const float* __restrict__ tf,
                       const float* __restrict__ pos,
                       float* __restrict__ out)
{
    __shared__ float s_sh[256];   // center pixel channel vector
    __shared__ float corr[32];    // 25 logits (+pad)

    const int pt  = blockIdx.x;          // 0 .. B*K-1
    const int b   = pt >> 10;            // K = 1024
    const int tid = threadIdx.x;         // = channel index

    const float pr = pos[2 * pt + 0];
    const float pc = pos[2 * pt + 1];
    const int r = (int)pr;               // positions >= 0 -> trunc == astype(int32)
    const int c = (int)pc;

    const float* fb = tf + (size_t)b * (H_ * W_ * C_);

    // Center pixel (always in-bounds: positions in [0, H-1]).
    const float s_own = fb[((size_t)r * W_ + c) * C_ + tid];
    s_sh[tid] = s_own;
    if (tid < 32) corr[tid] = 0.0f;
    __syncthreads();

    // Thread's products: idx = 25*tid + p, p = 0..24. Token n = idx >> 8.
    // idx spans 25 values -> at most one token boundary.
    const int idx0  = 25 * tid;
    const int n0    = idx0 >> 8;
    const int split = ((n0 + 1) << 8) - idx0;   // p >= split -> token n0+1
    const int j0    = idx0 & 255;               // s index base (j = (idx0+p)&255)

    float a0 = 0.0f, a1 = 0.0f;

    #pragma unroll
    for (int p = 0; p < 25; ++p) {
        const int dy = p / 5, dx = p % 5;
        const int rr = r - 2 + dy;
        const int cc = c - 2 + dx;
        float v;
        if (p == 12) {
            v = s_own;                           // center: already in register
        } else {
            v = 0.0f;
            if (rr >= 0 && rr < H_ && cc >= 0 && cc < W_)
                v = fb[((size_t)rr * W_ + cc) * C_ + tid];   // coalesced per warp
        }
        const float sv = s_sh[(j0 + p) & 255];   // lane stride 25 -> conflict-free
        const float t  = v * sv;
        if (p < split) a0 += t; else a1 += t;
    }

    atomicAdd(&corr[n0], a0);
    if (split < 25) atomicAdd(&corr[n0 + 1], a1);
    __syncthreads();

    // Warp 0: softmax over 25 logits + expected offset.
    if (tid < 32) {
        const int lane = tid;
        const float v = (lane < 25) ? corr[lane] : -INFINITY;
        float m = v;
        #pragma unroll
        for (int o = 16; o > 0; o >>= 1)
            m = fmaxf(m, __shfl_xor_sync(0xffffffffu, m, o));
        float e = (lane < 25) ? expf(v - m) : 0.0f;
        float ssum = e;
        #pragma unroll
        for (int o = 16; o > 0; o >>= 1)
            ssum += __shfl_xor_sync(0xffffffffu, ssum, o);
        const float prb = e / ssum;              // 0 for lane >= 25

        // offsets: linspace(-3, 2, 5) = -3 + 1.25*i (exact fp32)
        const int ir = lane / 5;
        const int ic = lane - ir * 5;
        float dr = prb * (-3.0f + 1.25f * (float)ir);
        float dc = prb * (-3.0f + 1.25f * (float)ic);
        #pragma unroll
        for (int o = 16; o > 0; o >>= 1) {
            dr += __shfl_xor_sync(0xffffffffu, dr, o);
            dc += __shfl_xor_sync(0xffffffffu, dc, o);
        }
        if (lane == 0) {
            out[2 * pt + 0] = pr + dr;
            out[2 * pt + 1] = pc + dc;
        }
    }
}

extern "C" void kernel_launch(void* const* d_in, const int* in_sizes, int n_in,
                              void* d_out, int out_size)
{
    (void)in_sizes; (void)n_in; (void)out_size;
    // metadata order: 0=source_features (unused by reference), 1=target_features,
    // 2=coarse_positions, 3..6 = Wq,Wk,Wv,Wo (cancel algebraically)
    const float* tf  = (const float*)d_in[1];
    const float* pos = (const float*)d_in[2];
    float* out = (float*)d_out;

    fine_match_kernel<<<B_ * K_, 256>>>(tf, pos, out);
}

// round 5
// speedup vs baseline: 1.3205x; 1.3205x over previous
#include <cuda_runtime.h>
#include <math.h>

// FineMatchingModule — algebraically collapsed (verified R3/R4, rel_err ~1.4e-8):
// both attention layers add only window-uniform shifts which the final softmax
// cancels. Per point:
//   corr[n] = sum_j s[j] * flat[n*256+j],  n = 0..24
// flat = channel-major-flattened zero-padded 5x5 window of target_features at
// the truncated coarse position; s = center pixel channel vector.
// refined = pos + softmax(corr) @ offsets, offsets1d = linspace(-3,2,5).
//
// R5: kill the MIO bottleneck. No atomics, no shuffles in the reduction path:
// per-thread dual accumulators -> conflict-free STS to pa/pb; token->thread
// mapping is STATIC (thread t's a0 feeds token (25t)>>8, a1 feeds the next),
// so warp 0 gathers each token's contiguous pa-run + one pb with plain LDS.
// Interior fast path: no bounds checks, single base pointer + immediate
// offsets. launch_bounds(256,6) -> 42 regs for deep load batching.

#define B_ 4
#define K_ 1024
#define H_ 256
#define W_ 256
#define C_ 256

__global__ __launch_bounds__(256, 6)
void fine_match_kernel(const float* __restrict__ tf,
                       const float* __restrict__ pos,
                       float* __restrict__ out)
{
    __shared__ float s_sh[280];    // center vector, first 24 entries doubled
    __shared__ float pa[256];      // per-thread partial -> token n0
    __shared__ float pb[256];      // per-thread partial -> token n0+1 (0 if none)

    const int pt  = blockIdx.x;          // 0 .. B*K-1
    const int b   = pt >> 10;            // K = 1024
    const int tid = threadIdx.x;         // = channel index

    const float pr = pos[2 * pt + 0];
    const float pc = pos[2 * pt + 1];
    const int r = (int)pr;               // positions >= 0 -> trunc == astype(int32)
    const int c = (int)pc;

    const float* fb = tf + (size_t)b * (H_ * W_ * C_);

    // Center pixel (always in-bounds).
    const float s_own = fb[((size_t)r * W_ + c) * C_ + tid];
    s_sh[tid] = s_own;
    if (tid < 24) s_sh[256 + tid] = s_own;   // wrap copy: avoids &255 per product
    __syncthreads();

    // Thread's products: idx = 25*tid + p, p = 0..24. Token n = idx >> 8.
    // At most one 256-boundary inside the 25-run -> two accumulators.
    const int j0    = (25 * tid) & 255;
    const int split = 256 - j0;          // p >= split -> token n0+1 (split >= 1)

    float a0 = 0.0f, a1 = 0.0f;

    const bool interior = (r >= 2) & (r <= H_ - 3) & (c >= 2) & (c <= W_ - 3);
    if (interior) {
        // One base pointer; every pixel is a compile-time immediate offset.
        const float* base = fb + ((size_t)(r - 2) * W_ + (c - 2)) * C_ + tid;
        #pragma unroll
        for (int p = 0; p < 25; ++p) {
            const int off = (p / 5) * (W_ * C_) + (p % 5) * C_;
            const float v = (p == 12) ? s_own : base[off];     // coalesced LDG
            const float t = v * s_sh[j0 + p];                  // conflict-free LDS
            if (p < split) a0 += t; else a1 += t;
        }
    } else {
        // Border path (~3% of CTAs, CTA-uniform): zero-padded OOB pixels.
        #pragma unroll
        for (int p = 0; p < 25; ++p) {
            const int rr = r - 2 + p / 5;
            const int cc = c - 2 + p % 5;
            float v;
            if (p == 12) {
                v = s_own;
            } else {
                v = 0.0f;
                if (rr >= 0 && rr < H_ && cc >= 0 && cc < W_)
                    v = fb[((size_t)rr * W_ + cc) * C_ + tid];
            }
            const float t = v * s_sh[j0 + p];
            if (p < split) a0 += t; else a1 += t;
        }
    }

    pa[tid] = a0;                        // plain STS — no atomics
    pb[tid] = a1;
    __syncthreads();

    // Warp 0: static gather per token, then softmax + expected offset.
    if (tid < 32) {
        const int lane = tid;
        float logit = -INFINITY;
        if (lane < 25) {
            // token n's a0-contributors: contiguous thread range [t0, t1];
            // plus thread t0-1's boundary tail (pb) for n >= 1.
            const int n  = lane;
            const int t0 = (256 * n + 24) / 25;
            const int t1 = (256 * n + 255) / 25;
            float sum = (n > 0) ? pb[t0 - 1] : 0.0f;
            for (int t = t0; t <= t1; ++t) sum += pa[t];   // <= 11 iters
            logit = sum;
        }
        float m = logit;
        #pragma unroll
        for (int o = 16; o > 0; o >>= 1)
            m = fmaxf(m, __shfl_xor_sync(0xffffffffu, m, o));
        float e = (lane < 25) ? expf(logit - m) : 0.0f;
        float ssum = e;
        #pragma unroll
        for (int o = 16; o > 0; o >>= 1)
            ssum += __shfl_xor_sync(0xffffffffu, ssum, o);
        const float prb = e / ssum;      // 0 for lane >= 25

        // offsets: linspace(-3, 2, 5) = -3 + 1.25*i (exact fp32)
        const int ir = lane / 5;
        const int ic = lane - ir * 5;
        float dr = prb * (-3.0f + 1.25f * (float)ir);
        float dc = prb * (-3.0f + 1.25f * (float)ic);
        #pragma unroll
        for (int o = 16; o > 0; o >>= 1) {
            dr += __shfl_xor_sync(0xffffffffu, dr, o);
            dc += __shfl_xor_sync(0xffffffffu, dc, o);
        }
        if (lane == 0) {
            out[2 * pt + 0] = pr + dr;
            out[2 * pt + 1] = pc + dc;
        }
    }
}

extern "C" void kernel_launch(void* const* d_in, const int* in_sizes, int n_in,
                              void* d_out, int out_size)
{
    (void)in_sizes; (void)n_in; (void)out_size;
    // metadata order: 0=source_features (unused by reference), 1=target_features,
    // 2=coarse_positions, 3..6 = Wq,Wk,Wv,Wo (cancel algebraically)
    const float* tf  = (const float*)d_in[1];
    const float* pos = (const float*)d_in[2];
    float* out = (float*)d_out;

    fine_match_kernel<<<B_ * K_, 256>>>(tf, pos, out);
}